// round 4
// baseline (speedup 1.0000x reference)
#include <cuda_runtime.h>

// Problem constants (shapes fixed by this dataset instance)
#define H 128
#define BM 64
#define NMAX 100096

// Scratch: agg buffer (also reused as h2), and h1 buffer. 16B-aligned for
// float4 / red.v4 access.
static __device__ __align__(16) float g_agg[(size_t)NMAX * H];
static __device__ __align__(16) float g_h1[(size_t)NMAX * H];

// ---------------------------------------------------------------------------
// f32x2 packed-FMA helpers (FFMA2 path — 2 fp32 FMAs per issue on sm_103a)
// ---------------------------------------------------------------------------
__device__ __forceinline__ unsigned long long pack2(float lo, float hi) {
    unsigned long long r;
    asm("mov.b64 %0, {%1, %2};" : "=l"(r) : "f"(lo), "f"(hi));
    return r;
}
__device__ __forceinline__ void fma2(unsigned long long& d, unsigned long long a,
                                     unsigned long long b) {
    asm("fma.rn.f32x2 %0, %1, %2, %0;" : "+l"(d) : "l"(a), "l"(b));
}
__device__ __forceinline__ void unpack2(unsigned long long v, float& lo, float& hi) {
    asm("mov.b64 {%0, %1}, %2;" : "=f"(lo), "=f"(hi) : "l"(v));
}

// ---------------------------------------------------------------------------
// Zero the aggregation buffer (atomics accumulate into it each call)
// ---------------------------------------------------------------------------
__global__ void zero_kernel(int n4) {
    float4* p = reinterpret_cast<float4*>(g_agg);
    int i = blockIdx.x * blockDim.x + threadIdx.x;
    int stride = gridDim.x * blockDim.x;
    float4 z = make_float4(0.f, 0.f, 0.f, 0.f);
    for (; i < n4; i += stride) p[i] = z;
}

// ---------------------------------------------------------------------------
// Scatter: agg[col[e]] += edge_attr[e]  via vectorized global reductions.
// One thread per (edge, 4-float chunk): 32 threads cover one edge's 128 floats.
// edge_index dtype is detected at runtime: JAX without x64 silently makes it
// int32; if it really were int64 (values < 2^31, little-endian), the odd
// 32-bit words of row 0 are all zero.
// ---------------------------------------------------------------------------
__global__ void scatter_kernel(const float* __restrict__ ea,
                               const int* __restrict__ ei32, int E) {
    long long i = (long long)blockIdx.x * blockDim.x + threadIdx.x;
    long long total = (long long)E * 32;
    if (i >= total) return;
    int e = (int)(i >> 5);
    int q = (int)(i & 31);

    // dtype probe (broadcast loads, L1-resident after first warp)
    bool is64 = ((ei32[1] | ei32[3] | ei32[5] | ei32[7]) == 0);
    int col = is64 ? ei32[2 * (E + e)] : ei32[E + e];

    float4 v = reinterpret_cast<const float4*>(ea)[(size_t)e * 32 + q];
    float* dst = g_agg + (size_t)col * H + q * 4;
    asm volatile("red.global.add.v4.f32 [%0], {%1,%2,%3,%4};"
                 :: "l"(dst), "f"(v.x), "f"(v.y), "f"(v.z), "f"(v.w)
                 : "memory");
}

// ---------------------------------------------------------------------------
// Fused layer: out = ssp(layer_norm(In @ W + b, g, be))
// In is [N,K] (K=256 for layer 1 via concat(x, agg), else K=128).
// Block: 256 threads, BM=64 rows. Thread (ty,tx) in 16x16 grid owns
// 4 rows x 8 cols. Accumulation in packed f32x2. LN reduced via shfl over
// the 16 lanes that share a row.
// ---------------------------------------------------------------------------
template <int K, bool CONCAT, int INS>
__global__ void layer_kernel(const float* __restrict__ inA,
                             const float* __restrict__ inB,
                             const float* __restrict__ W,
                             const float* __restrict__ bias,
                             const float* __restrict__ gam,
                             const float* __restrict__ bet,
                             float* __restrict__ out, int N) {
    extern __shared__ float smem[];
    float* sW = smem;             // [K][H]
    float* sIn = smem + K * H;    // [BM][INS] (padded rows to dodge bank conflicts)

    const int tid = threadIdx.x;
    const int row0 = blockIdx.x * BM;

    // Stage W (row-major [K][H]) into smem, float4-wide.
    #pragma unroll 4
    for (int i = tid; i < K * H / 4; i += 256)
        reinterpret_cast<float4*>(sW)[i] = reinterpret_cast<const float4*>(W)[i];

    // Stage input tile [BM][K].
    constexpr int F4 = K / 4;
    for (int i = tid; i < BM * F4; i += 256) {
        int r = i / F4, kc = i % F4;
        int row = row0 + r;
        float4 v = make_float4(0.f, 0.f, 0.f, 0.f);
        if (row < N) {
            if (CONCAT) {
                v = (kc < 32)
                        ? reinterpret_cast<const float4*>(inA)[(size_t)row * 32 + kc]
                        : reinterpret_cast<const float4*>(inB)[(size_t)row * 32 + (kc - 32)];
            } else {
                v = reinterpret_cast<const float4*>(inA)[(size_t)row * 32 + kc];
            }
        }
        *reinterpret_cast<float4*>(&sIn[r * INS + kc * 4]) = v;
    }
    __syncthreads();

    const int ty = tid >> 4, tx = tid & 15;
    const int c0 = tx * 8;
    const int r0 = ty * 4;

    unsigned long long acc[4][4];
    #pragma unroll
    for (int i = 0; i < 4; i++)
        #pragma unroll
        for (int j = 0; j < 4; j++) acc[i][j] = 0ULL;

    #pragma unroll 4
    for (int k = 0; k < K; k++) {
        // 8 weight values for this thread's columns, pair-packed for f32x2.
        ulonglong2 w01 = *reinterpret_cast<const ulonglong2*>(&sW[k * H + c0]);
        ulonglong2 w23 = *reinterpret_cast<const ulonglong2*>(&sW[k * H + c0 + 4]);
        #pragma unroll
        for (int i = 0; i < 4; i++) {
            float a = sIn[(r0 + i) * INS + k];
            unsigned long long av = pack2(a, a);
            fma2(acc[i][0], av, w01.x);
            fma2(acc[i][1], av, w01.y);
            fma2(acc[i][2], av, w23.x);
            fma2(acc[i][3], av, w23.y);
        }
    }

    // Epilogue: bias + LayerNorm + shifted softplus, fused.
    float gv[8], bv[8], biasv[8];
    #pragma unroll
    for (int j = 0; j < 8; j++) {
        gv[j] = gam[c0 + j];
        bv[j] = bet[c0 + j];
        biasv[j] = bias[c0 + j];
    }

    #pragma unroll
    for (int i = 0; i < 4; i++) {
        int row = row0 + r0 + i;
        float v[8];
        #pragma unroll
        for (int j = 0; j < 4; j++) unpack2(acc[i][j], v[2 * j], v[2 * j + 1]);
        float s = 0.f, q = 0.f;
        #pragma unroll
        for (int j = 0; j < 8; j++) {
            v[j] += biasv[j];
            s += v[j];
            q += v[j] * v[j];
        }
        // Reduce across the 16 lanes sharing this row (xor masks < 16 stay in-group).
        #pragma unroll
        for (int m = 8; m >= 1; m >>= 1) {
            s += __shfl_xor_sync(0xffffffffu, s, m);
            q += __shfl_xor_sync(0xffffffffu, q, m);
        }
        float mean = s * (1.0f / 128.0f);
        float var = q * (1.0f / 128.0f) - mean * mean;
        float rs = rsqrtf(var + 1e-5f);
        float o[8];
        #pragma unroll
        for (int j = 0; j < 8; j++) {
            float y = (v[j] - mean) * rs * gv[j] + bv[j];
            // stable softplus(y) - ln(2)
            float sp = fmaxf(y, 0.0f) + log1pf(expf(-fabsf(y)));
            o[j] = sp - 0.6931471805599453f;
        }
        if (row < N) {
            float4* op = reinterpret_cast<float4*>(out + (size_t)row * H + c0);
            op[0] = make_float4(o[0], o[1], o[2], o[3]);
            op[1] = make_float4(o[4], o[5], o[6], o[7]);
        }
    }
}

// ---------------------------------------------------------------------------
// Launch
// ---------------------------------------------------------------------------
extern "C" void kernel_launch(void* const* d_in, const int* in_sizes, int n_in,
                              void* d_out, int out_size) {
    const float* x       = (const float*)d_in[0];
    const int* ei        = (const int*)d_in[1];   // edge_index (int32; int64 probed at runtime)
    const float* ea      = (const float*)d_in[2];
    const float* W1      = (const float*)d_in[3];
    const float* b1      = (const float*)d_in[4];
    const float* g1      = (const float*)d_in[5];
    const float* be1     = (const float*)d_in[6];
    const float* W2      = (const float*)d_in[7];
    const float* b2      = (const float*)d_in[8];
    const float* g2      = (const float*)d_in[9];
    const float* be2     = (const float*)d_in[10];
    const float* W3      = (const float*)d_in[11];
    const float* b3      = (const float*)d_in[12];
    const float* g3      = (const float*)d_in[13];
    const float* be3     = (const float*)d_in[14];

    const int N = in_sizes[0] / H;
    const int E = in_sizes[1] / 2;

    float* agg = nullptr;
    float* h1 = nullptr;
    cudaGetSymbolAddress((void**)&agg, g_agg);
    cudaGetSymbolAddress((void**)&h1, g_h1);

    constexpr int SMEM1 = (256 * H + BM * 260) * (int)sizeof(float);  // ~193 KB
    constexpr int SMEM2 = (128 * H + BM * 132) * (int)sizeof(float);  // ~97 KB
    cudaFuncSetAttribute(layer_kernel<256, true, 260>,
                         cudaFuncAttributeMaxDynamicSharedMemorySize, SMEM1);
    cudaFuncSetAttribute(layer_kernel<128, false, 132>,
                         cudaFuncAttributeMaxDynamicSharedMemorySize, SMEM2);

    // 1) zero agg
    {
        int n4 = N * (H / 4);
        zero_kernel<<<592, 256>>>(n4);
    }
    // 2) scatter edges into agg
    {
        long long total = (long long)E * 32;
        int blocks = (int)((total + 255) / 256);
        scatter_kernel<<<blocks, 256>>>(ea, ei, E);
    }
    // 3) three fused layers
    int nb = (N + BM - 1) / BM;
    layer_kernel<256, true, 260><<<nb, 256, SMEM1>>>(x, agg, W1, b1, g1, be1, h1, N);
    layer_kernel<128, false, 132><<<nb, 256, SMEM2>>>(h1, nullptr, W2, b2, g2, be2, agg, N);
    layer_kernel<128, false, 132><<<nb, 256, SMEM2>>>(agg, nullptr, W3, b3, g3, be3,
                                                      (float*)d_out, N);
}

// round 6
// speedup vs baseline: 1.2648x; 1.2648x over previous
#include <cuda_runtime.h>

// Problem constants (shapes fixed by this dataset instance)
#define H 128
#define NMAX 100096

// Scratch: agg buffer (also reused as h2), and h1 buffer. 16B-aligned.
static __device__ __align__(16) float g_agg[(size_t)NMAX * H];
static __device__ __align__(16) float g_h1[(size_t)NMAX * H];

// ---------------------------------------------------------------------------
// f32x2 packed-FMA helpers (FFMA2 path — 2 fp32 FMAs per issue on sm_103a)
// ---------------------------------------------------------------------------
__device__ __forceinline__ unsigned long long pack2(float lo, float hi) {
    unsigned long long r;
    asm("mov.b64 %0, {%1, %2};" : "=l"(r) : "f"(lo), "f"(hi));
    return r;
}
__device__ __forceinline__ void fma2(unsigned long long& d, unsigned long long a,
                                     unsigned long long b) {
    asm("fma.rn.f32x2 %0, %1, %2, %0;" : "+l"(d) : "l"(a), "l"(b));
}
__device__ __forceinline__ void unpack2(unsigned long long v, float& lo, float& hi) {
    asm("mov.b64 {%0, %1}, %2;" : "=f"(lo), "=f"(hi) : "l"(v));
}

// ---------------------------------------------------------------------------
// Zero the aggregation buffer (atomics accumulate into it each call)
// ---------------------------------------------------------------------------
__global__ void zero_kernel(int n4) {
    float4* p = reinterpret_cast<float4*>(g_agg);
    int i = blockIdx.x * blockDim.x + threadIdx.x;
    int stride = gridDim.x * blockDim.x;
    float4 z = make_float4(0.f, 0.f, 0.f, 0.f);
    for (; i < n4; i += stride) p[i] = z;
}

// ---------------------------------------------------------------------------
// Scatter: agg[col[e]] += edge_attr[e]  via vectorized global reductions.
// 32 threads per edge (one float4 chunk each). edge_index dtype probed at
// runtime (JAX w/o x64 silently gives int32; int64 would have zero odd words).
// ---------------------------------------------------------------------------
__global__ void scatter_kernel(const float* __restrict__ ea,
                               const int* __restrict__ ei32, int E) {
    long long i = (long long)blockIdx.x * blockDim.x + threadIdx.x;
    long long total = (long long)E * 32;
    if (i >= total) return;
    int e = (int)(i >> 5);
    int q = (int)(i & 31);

    bool is64 = ((ei32[1] | ei32[3] | ei32[5] | ei32[7]) == 0);
    int col = is64 ? ei32[2 * (E + e)] : ei32[E + e];

    float4 v = reinterpret_cast<const float4*>(ea)[(size_t)e * 32 + q];
    float* dst = g_agg + (size_t)col * H + q * 4;
    asm volatile("red.global.add.v4.f32 [%0], {%1,%2,%3,%4};"
                 :: "l"(dst), "f"(v.x), "f"(v.y), "f"(v.z), "f"(v.w)
                 : "memory");
}

// ---------------------------------------------------------------------------
// Fused layer: out = ssp(layer_norm(In @ W + b, g, be))
//
// Layout (the L1-pressure fix):
//  - input staged TRANSPOSED in smem: sInT[k][row] (stride BM+2, conflict-free)
//  - W staged in 128-k chunks: sW[128][H]; weight reads are warp-UNIFORM
//    LDS.128 broadcasts (1 wavefront each)
//  - warp = 64 rows x 32 cols; lane = rows (2*lane, 2*lane+1) x 32 cols
//    -> per warp-k: 1 LDS.64 + 8 broadcast LDS.128 vs 32 FFMA2 (64 fma-cyc)
//  - LayerNorm: per-lane partial (32 cols), cross-warp reduce via smem.
// ---------------------------------------------------------------------------
template <int K, int BM, int NT, bool CONCAT>
__global__ __launch_bounds__(NT, 1)
void layer_kernel(const float* __restrict__ inA,
                  const float* __restrict__ inB,
                  const float* __restrict__ W,
                  const float* __restrict__ bias,
                  const float* __restrict__ gam,
                  const float* __restrict__ bet,
                  float* __restrict__ out, int N) {
    constexpr int STRIDE = BM + 2;   // even (LDS.64 align), odd/32 bank walk via row
    extern __shared__ float smem[];
    float* sW = smem;                 // [128][H] one k-chunk (64 KB)
    float* sInT = smem + 128 * H;     // [K][STRIDE]

    const int tid = threadIdx.x;
    const int row0blk = blockIdx.x * BM;

    // ---- Stage input transposed: sInT[k][r] ----
    constexpr int F4 = K / 4;
    for (int i = tid; i < BM * F4; i += NT) {
        int r = i % BM;          // consecutive tid -> consecutive rows: STS conflict-free
        int kc = i / BM;
        int row = row0blk + r;
        float4 v = make_float4(0.f, 0.f, 0.f, 0.f);
        if (row < N) {
            if (CONCAT) {
                v = (kc < 32)
                        ? reinterpret_cast<const float4*>(inA)[(size_t)row * 32 + kc]
                        : reinterpret_cast<const float4*>(inB)[(size_t)row * 32 + (kc - 32)];
            } else {
                v = reinterpret_cast<const float4*>(inA)[(size_t)row * 32 + kc];
            }
        }
        sInT[(4 * kc + 0) * STRIDE + r] = v.x;
        sInT[(4 * kc + 1) * STRIDE + r] = v.y;
        sInT[(4 * kc + 2) * STRIDE + r] = v.z;
        sInT[(4 * kc + 3) * STRIDE + r] = v.w;
    }

    const int wid = tid >> 5;
    const int lane = tid & 31;
    const int wr = wid >> 2;           // row-group of warp
    const int wc = wid & 3;            // col-group of warp
    const int rloc = wr * 64 + 2 * lane;   // first of this lane's row pair
    const int c0 = wc * 32;                // this warp's 32 columns

    unsigned long long acc0[16], acc1[16];
    #pragma unroll
    for (int p = 0; p < 16; p++) { acc0[p] = 0ULL; acc1[p] = 0ULL; }

    // ---- Main loop over k-chunks of 128 ----
    for (int kc = 0; kc < K; kc += 128) {
        __syncthreads();   // previous chunk's sW readers done / sInT staged
        #pragma unroll 4
        for (int i = tid; i < 128 * H / 4; i += NT)
            reinterpret_cast<float4*>(sW)[i] =
                reinterpret_cast<const float4*>(W + (size_t)kc * H)[i];
        __syncthreads();

        const float* sInk = sInT + kc * STRIDE + rloc;
        #pragma unroll 2
        for (int k = 0; k < 128; k++) {
            float2 a = *reinterpret_cast<const float2*>(sInk + k * STRIDE);
            unsigned long long av0 = pack2(a.x, a.x);
            unsigned long long av1 = pack2(a.y, a.y);
            const float* wrow = &sW[k * H + c0];
            #pragma unroll
            for (int jj = 0; jj < 8; jj++) {
                ulonglong2 w = *reinterpret_cast<const ulonglong2*>(wrow + 4 * jj);
                fma2(acc0[2 * jj + 0], av0, w.x);
                fma2(acc0[2 * jj + 1], av0, w.y);
                fma2(acc1[2 * jj + 0], av1, w.x);
                fma2(acc1[2 * jj + 1], av1, w.y);
            }
        }
    }

    // ---- Epilogue: bias + LayerNorm (cross-warp via smem) + ssp ----
    __syncthreads();                        // everyone done reading sW
    float2* sRed = reinterpret_cast<float2*>(smem);   // [BM][5] padded (in sW area)

    float v0[32], v1[32];
    float s0 = 0.f, q0 = 0.f, s1 = 0.f, q1 = 0.f;
    #pragma unroll
    for (int p = 0; p < 16; p++) {
        float b0 = bias[c0 + 2 * p], b1 = bias[c0 + 2 * p + 1];
        float x0, x1;
        unpack2(acc0[p], x0, x1);
        x0 += b0; x1 += b1;
        v0[2 * p] = x0; v0[2 * p + 1] = x1;
        s0 += x0 + x1; q0 += x0 * x0 + x1 * x1;
        unpack2(acc1[p], x0, x1);
        x0 += b0; x1 += b1;
        v1[2 * p] = x0; v1[2 * p + 1] = x1;
        s1 += x0 + x1; q1 += x0 * x0 + x1 * x1;
    }
    sRed[rloc * 5 + wc] = make_float2(s0, q0);
    sRed[(rloc + 1) * 5 + wc] = make_float2(s1, q1);
    __syncthreads();

    float2 t0 = make_float2(0.f, 0.f), t1 = make_float2(0.f, 0.f);
    #pragma unroll
    for (int j = 0; j < 4; j++) {
        float2 a = sRed[rloc * 5 + j];
        float2 b = sRed[(rloc + 1) * 5 + j];
        t0.x += a.x; t0.y += a.y;
        t1.x += b.x; t1.y += b.y;
    }
    const float inv = 1.0f / 128.0f;
    float mean0 = t0.x * inv, mean1 = t1.x * inv;
    float rs0 = rsqrtf(t0.y * inv - mean0 * mean0 + 1e-5f);
    float rs1 = rsqrtf(t1.y * inv - mean1 * mean1 + 1e-5f);

    const int rowg0 = row0blk + rloc;
    const bool ok0 = rowg0 < N, ok1 = (rowg0 + 1) < N;
    const float LN2 = 0.6931471805599453f;
    #pragma unroll
    for (int jj = 0; jj < 8; jj++) {       // 4 cols at a time
        float4 g4 = reinterpret_cast<const float4*>(gam)[(c0 >> 2) + jj];
        float4 e4 = reinterpret_cast<const float4*>(bet)[(c0 >> 2) + jj];
        float go[4] = {g4.x, g4.y, g4.z, g4.w};
        float eo[4] = {e4.x, e4.y, e4.z, e4.w};
        float o0[4], o1[4];
        #pragma unroll
        for (int j = 0; j < 4; j++) {
            float y0 = (v0[4 * jj + j] - mean0) * rs0 * go[j] + eo[j];
            float y1 = (v1[4 * jj + j] - mean1) * rs1 * go[j] + eo[j];
            o0[j] = fmaxf(y0, 0.f) + log1pf(expf(-fabsf(y0))) - LN2;
            o1[j] = fmaxf(y1, 0.f) + log1pf(expf(-fabsf(y1))) - LN2;
        }
        if (ok0)
            reinterpret_cast<float4*>(out + (size_t)rowg0 * H + c0)[jj] =
                make_float4(o0[0], o0[1], o0[2], o0[3]);
        if (ok1)
            reinterpret_cast<float4*>(out + (size_t)(rowg0 + 1) * H + c0)[jj] =
                make_float4(o1[0], o1[1], o1[2], o1[3]);
    }
}

// ---------------------------------------------------------------------------
// Launch
// ---------------------------------------------------------------------------
extern "C" void kernel_launch(void* const* d_in, const int* in_sizes, int n_in,
                              void* d_out, int out_size) {
    const float* x   = (const float*)d_in[0];
    const int* ei    = (const int*)d_in[1];
    const float* ea  = (const float*)d_in[2];
    const float* W1  = (const float*)d_in[3];
    const float* b1  = (const float*)d_in[4];
    const float* g1  = (const float*)d_in[5];
    const float* be1 = (const float*)d_in[6];
    const float* W2  = (const float*)d_in[7];
    const float* b2  = (const float*)d_in[8];
    const float* g2  = (const float*)d_in[9];
    const float* be2 = (const float*)d_in[10];
    const float* W3  = (const float*)d_in[11];
    const float* b3  = (const float*)d_in[12];
    const float* g3  = (const float*)d_in[13];
    const float* be3 = (const float*)d_in[14];

    const int N = in_sizes[0] / H;
    const int E = in_sizes[1] / 2;

    float* agg = nullptr;
    float* h1 = nullptr;
    cudaGetSymbolAddress((void**)&agg, g_agg);
    cudaGetSymbolAddress((void**)&h1, g_h1);

    // Layer 1: K=256, BM=128, NT=256. smem = 64KB (sW chunk) + 256*130*4
    constexpr int SMEM1 = (128 * H + 256 * 130) * (int)sizeof(float);  // ~194 KB
    // Layers 2/3: K=128, BM=256, NT=512. smem = 64KB + 128*258*4
    constexpr int SMEM2 = (128 * H + 128 * 258) * (int)sizeof(float);  // ~193 KB
    cudaFuncSetAttribute((const void*)layer_kernel<256, 128, 256, true>,
                         cudaFuncAttributeMaxDynamicSharedMemorySize, SMEM1);
    cudaFuncSetAttribute((const void*)layer_kernel<128, 256, 512, false>,
                         cudaFuncAttributeMaxDynamicSharedMemorySize, SMEM2);

    // 1) zero agg
    zero_kernel<<<592, 256>>>(N * (H / 4));
    // 2) scatter edges into agg
    {
        long long total = (long long)E * 32;
        int blocks = (int)((total + 255) / 256);
        scatter_kernel<<<blocks, 256>>>(ea, ei, E);
    }
    // 3) three fused layers
    int nb1 = (N + 127) / 128;
    int nb2 = (N + 255) / 256;
    layer_kernel<256, 128, 256, true><<<nb1, 256, SMEM1>>>(x, agg, W1, b1, g1, be1, h1, N);
    layer_kernel<128, 256, 512, false><<<nb2, 512, SMEM2>>>(h1, nullptr, W2, b2, g2, be2, agg, N);
    layer_kernel<128, 256, 512, false><<<nb2, 512, SMEM2>>>(agg, nullptr, W3, b3, g3, be3,
                                                            (float*)d_out, N);
}

// round 14
// speedup vs baseline: 2.0985x; 1.6592x over previous
#include <cuda_runtime.h>
#include <cuda_bf16.h>
#include <cstdint>

#define H 128
#define NMAX 100096

// Scratch + pre-swizzled bf16 weight images: 4 chunks x (32KB hi + 32KB lo).
// chunk0 = W1[k<128], chunk1 = W1[k>=128], chunk2 = W2, chunk3 = W3.
static __device__ __align__(16) float g_agg[(size_t)NMAX * H];
static __device__ __align__(16) float g_h1[(size_t)NMAX * H];
static __device__ __align__(16) unsigned char g_wimg[4 * 65536];

// ---------------------------------------------------------------------------
// Swizzled [row][k] bf16 tile addressing: rowbytes=256 (128 bf16), XOR-16B
// swizzle on (row&7) -> conflict-free LDSM / STS.
// ---------------------------------------------------------------------------
__device__ __forceinline__ int sw(int r, int kbyte) {
    return r * 256 + (kbyte ^ ((r & 7) << 4));
}

// ldmatrix x4 (non-transposed, b16)
#define LDSM_X4(r0, r1, r2, r3, addr) \
    asm volatile("ldmatrix.sync.aligned.m8n8.x4.shared.b16 {%0,%1,%2,%3}, [%4];" \
                 : "=r"(r0), "=r"(r1), "=r"(r2), "=r"(r3) : "r"(addr))

// bf16 mma with fp32 accumulate
#define MMA_BF16(c, a0, a1, a2, a3, b0, b1) \
    asm volatile("mma.sync.aligned.m16n8k16.row.col.f32.bf16.bf16.f32 " \
                 "{%0,%1,%2,%3}, {%4,%5,%6,%7}, {%8,%9}, {%0,%1,%2,%3};" \
                 : "+f"((c)[0]), "+f"((c)[1]), "+f"((c)[2]), "+f"((c)[3]) \
                 : "r"(a0), "r"(a1), "r"(a2), "r"(a3), "r"(b0), "r"(b1))

__device__ __forceinline__ uint32_t smem_u32(const void* p) {
    uint32_t a;
    asm("{ .reg .u64 t; cvta.to.shared.u64 t, %1; cvt.u32.u64 %0, t; }"
        : "=r"(a) : "l"(p));
    return a;
}

// hi/lo bf16 split-store of a float4 (4 elems = 8B hi + 8B lo)
__device__ __forceinline__ void split_store(char* base, int off, float4 v, int lo_delta) {
    __nv_bfloat162 hA = __floats2bfloat162_rn(v.x, v.y);
    __nv_bfloat162 hB = __floats2bfloat162_rn(v.z, v.w);
    float2 fA = __bfloat1622float2(hA);
    float2 fB = __bfloat1622float2(hB);
    __nv_bfloat162 lA = __floats2bfloat162_rn(v.x - fA.x, v.y - fA.y);
    __nv_bfloat162 lB = __floats2bfloat162_rn(v.z - fB.x, v.w - fB.y);
    *reinterpret_cast<uint2*>(base + off) =
        make_uint2(*reinterpret_cast<unsigned*>(&hA), *reinterpret_cast<unsigned*>(&hB));
    *reinterpret_cast<uint2*>(base + lo_delta + off) =
        make_uint2(*reinterpret_cast<unsigned*>(&lA), *reinterpret_cast<unsigned*>(&lB));
}

// ---------------------------------------------------------------------------
// Weight pre-convert: W[k][n] f32 -> [n][k] swizzled bf16 hi/lo images.
// ---------------------------------------------------------------------------
__global__ void wconv_kernel(const float* __restrict__ W1, const float* __restrict__ W2,
                             const float* __restrict__ W3) {
    int i = blockIdx.x * 256 + threadIdx.x;
    if (i >= 4 * 16384) return;
    int chunk = i >> 14;
    int idx = i & 16383;
    int n = idx & 127;   // consecutive threads -> consecutive n: coalesced LDG
    int k = idx >> 7;
    const float* W = (chunk < 2) ? W1 : (chunk == 2 ? W2 : W3);
    int krow = (chunk == 1) ? k + 128 : k;
    float w = W[krow * H + n];
    __nv_bfloat16 hi = __float2bfloat16(w);
    __nv_bfloat16 lo = __float2bfloat16(w - __bfloat162float(hi));
    unsigned char* base = g_wimg + (size_t)chunk * 65536;
    int off = sw(n, k * 2);
    *reinterpret_cast<__nv_bfloat16*>(base + off) = hi;
    *reinterpret_cast<__nv_bfloat16*>(base + 32768 + off) = lo;
}

// ---------------------------------------------------------------------------
// Fused layer via mma.sync bf16 split-precision.
// smem: [A_hi 32K][A_lo 32K][B_hi 32K][B_lo 32K][params 1.5K]
// Block: 256 threads (8 warps). Warp w owns rows [16w,16w+16), all 128 cols.
// ---------------------------------------------------------------------------
#define SM_A 0
#define SM_B 65536
#define SM_P 131072
#define L_SMEM (131072 + 2048)

template <int NCHUNK>
__global__ __launch_bounds__(256, 1)
void layer_mma(const float* __restrict__ in0, const float* __restrict__ in1,
               const unsigned char* __restrict__ wimg,
               const float* __restrict__ bias, const float* __restrict__ gam,
               const float* __restrict__ bet, float* __restrict__ out, int N) {
    extern __shared__ char smem[];
    const int tid = threadIdx.x;
    const int lane = tid & 31;
    const int wid = tid >> 5;
    const int row0 = blockIdx.x * 128;
    const uint32_t sb = smem_u32(smem);

    float* sBias = reinterpret_cast<float*>(smem + SM_P);
    float* sG = sBias + 128;
    float* sBe = sG + 128;
    if (tid < 128) {
        sBias[tid] = bias[tid];
        sG[tid] = gam[tid];
        sBe[tid] = bet[tid];
    }

    float acc[16][4];
    #pragma unroll
    for (int j = 0; j < 16; j++)
        #pragma unroll
        for (int u = 0; u < 4; u++) acc[j][u] = 0.f;

    const int wbase = wid * 16;
    // Lane-invariant parts of LDSM addressing
    const int rowA = wbase + (lane & 15);
    const uint32_t aBase = sb + SM_A + rowA * 256;     // + (kb ^ xorA)
    const int xorA = (rowA & 7) << 4;
    const int kbSelA = (lane >> 4) << 4;               // +16 for lanes 16..31
    const int nLane = lane & 7;
    const uint32_t bBase0 = sb + SM_B + ((lane >> 4) & 1) * 32768 + nLane * 256;
    const int xorB = nLane << 4;
    const int kbSelB = ((lane >> 3) & 1) << 4;         // +16 for lanes 8-15 / 24-31

    #pragma unroll
    for (int c = 0; c < NCHUNK; c++) {
        if (c > 0) __syncthreads();   // previous chunk's LDSM done before restage
        // Stage A chunk: [128 rows][128 k] f32 -> swizzled bf16 hi/lo
        const float* src = (c == 0) ? in0 : in1;
        #pragma unroll 4
        for (int i = tid; i < 4096; i += 256) {
            int r = i >> 5, kc = i & 31;
            int row = row0 + r;
            float4 v = make_float4(0.f, 0.f, 0.f, 0.f);
            if (row < N) v = reinterpret_cast<const float4*>(src)[(size_t)row * 32 + kc];
            split_store(smem + SM_A, sw(r, kc * 8), v, 32768);
        }
        // Stage B chunk (identity copy of pre-swizzled 64KB image)
        #pragma unroll 4
        for (int i = tid; i < 4096; i += 256)
            reinterpret_cast<uint4*>(smem + SM_B)[i] =
                reinterpret_cast<const uint4*>(wimg + (size_t)c * 65536)[i];
        __syncthreads();

        // MMA phase: 8 k-steps of 16
        #pragma unroll
        for (int s = 0; s < 8; s++) {
            uint32_t aaddr = aBase + ((s * 32 + kbSelA) ^ xorA);
            uint32_t ah0, ah1, ah2, ah3, al0, al1, al2, al3;
            LDSM_X4(ah0, ah1, ah2, ah3, aaddr);
            LDSM_X4(al0, al1, al2, al3, aaddr + 32768);
            uint32_t bbase = bBase0 + ((s * 32 + kbSelB) ^ xorB);
            #pragma unroll
            for (int j = 0; j < 16; j++) {
                uint32_t bh0, bh1, bl0, bl1;
                LDSM_X4(bh0, bh1, bl0, bl1, bbase + j * 2048);
                MMA_BF16(acc[j], ah0, ah1, ah2, ah3, bh0, bh1);
                MMA_BF16(acc[j], ah0, ah1, ah2, ah3, bl0, bl1);
                MMA_BF16(acc[j], al0, al1, al2, al3, bh0, bh1);
            }
        }
    }

    // ---- Epilogue: bias + LayerNorm + shifted softplus ----
    const int g = lane >> 2, tg = lane & 3;
    const int r0g = row0 + wbase + g;
    const int r1g = r0g + 8;
    float s0 = 0.f, q0 = 0.f, s1 = 0.f, q1 = 0.f;
    #pragma unroll
    for (int j = 0; j < 16; j++) {
        float2 b = *reinterpret_cast<const float2*>(&sBias[j * 8 + 2 * tg]);
        acc[j][0] += b.x; acc[j][1] += b.y;
        acc[j][2] += b.x; acc[j][3] += b.y;
        s0 += acc[j][0] + acc[j][1];
        q0 += acc[j][0] * acc[j][0] + acc[j][1] * acc[j][1];
        s1 += acc[j][2] + acc[j][3];
        q1 += acc[j][2] * acc[j][2] + acc[j][3] * acc[j][3];
    }
    #pragma unroll
    for (int m = 1; m <= 2; m <<= 1) {
        s0 += __shfl_xor_sync(0xffffffffu, s0, m);
        q0 += __shfl_xor_sync(0xffffffffu, q0, m);
        s1 += __shfl_xor_sync(0xffffffffu, s1, m);
        q1 += __shfl_xor_sync(0xffffffffu, q1, m);
    }
    const float inv = 1.0f / 128.0f;
    float mean0 = s0 * inv, mean1 = s1 * inv;
    float rs0 = rsqrtf(q0 * inv - mean0 * mean0 + 1e-5f);
    float rs1 = rsqrtf(q1 * inv - mean1 * mean1 + 1e-5f);
    const float LN2 = 0.6931471805599453f;
    const bool ok0 = r0g < N, ok1 = r1g < N;
    #pragma unroll
    for (int j = 0; j < 16; j++) {
        int col = j * 8 + 2 * tg;
        float2 gv = *reinterpret_cast<const float2*>(&sG[col]);
        float2 ev = *reinterpret_cast<const float2*>(&sBe[col]);
        float y00 = (acc[j][0] - mean0) * rs0 * gv.x + ev.x;
        float y01 = (acc[j][1] - mean0) * rs0 * gv.y + ev.y;
        float y10 = (acc[j][2] - mean1) * rs1 * gv.x + ev.x;
        float y11 = (acc[j][3] - mean1) * rs1 * gv.y + ev.y;
        float2 o0 = make_float2(
            fmaxf(y00, 0.f) + log1pf(__expf(-fabsf(y00))) - LN2,
            fmaxf(y01, 0.f) + log1pf(__expf(-fabsf(y01))) - LN2);
        float2 o1 = make_float2(
            fmaxf(y10, 0.f) + log1pf(__expf(-fabsf(y10))) - LN2,
            fmaxf(y11, 0.f) + log1pf(__expf(-fabsf(y11))) - LN2);
        if (ok0) *reinterpret_cast<float2*>(out + (size_t)r0g * H + col) = o0;
        if (ok1) *reinterpret_cast<float2*>(out + (size_t)r1g * H + col) = o1;
    }
}

// ---------------------------------------------------------------------------
// Zero + scatter (unchanged)
// ---------------------------------------------------------------------------
__global__ void zero_kernel(int n4) {
    float4* p = reinterpret_cast<float4*>(g_agg);
    int i = blockIdx.x * blockDim.x + threadIdx.x;
    int stride = gridDim.x * blockDim.x;
    float4 z = make_float4(0.f, 0.f, 0.f, 0.f);
    for (; i < n4; i += stride) p[i] = z;
}

__global__ void scatter_kernel(const float* __restrict__ ea,
                               const int* __restrict__ ei32, int E) {
    long long i = (long long)blockIdx.x * blockDim.x + threadIdx.x;
    long long total = (long long)E * 32;
    if (i >= total) return;
    int e = (int)(i >> 5);
    int q = (int)(i & 31);
    bool is64 = ((ei32[1] | ei32[3] | ei32[5] | ei32[7]) == 0);
    int col = is64 ? ei32[2 * (E + e)] : ei32[E + e];
    float4 v = reinterpret_cast<const float4*>(ea)[(size_t)e * 32 + q];
    float* dst = g_agg + (size_t)col * H + q * 4;
    asm volatile("red.global.add.v4.f32 [%0], {%1,%2,%3,%4};"
                 :: "l"(dst), "f"(v.x), "f"(v.y), "f"(v.z), "f"(v.w)
                 : "memory");
}

// ---------------------------------------------------------------------------
// Launch
// ---------------------------------------------------------------------------
extern "C" void kernel_launch(void* const* d_in, const int* in_sizes, int n_in,
                              void* d_out, int out_size) {
    const float* x   = (const float*)d_in[0];
    const int* ei    = (const int*)d_in[1];
    const float* ea  = (const float*)d_in[2];
    const float* W1  = (const float*)d_in[3];
    const float* b1  = (const float*)d_in[4];
    const float* g1  = (const float*)d_in[5];
    const float* be1 = (const float*)d_in[6];
    const float* W2  = (const float*)d_in[7];
    const float* b2  = (const float*)d_in[8];
    const float* g2  = (const float*)d_in[9];
    const float* be2 = (const float*)d_in[10];
    const float* W3  = (const float*)d_in[11];
    const float* b3  = (const float*)d_in[12];
    const float* g3  = (const float*)d_in[13];
    const float* be3 = (const float*)d_in[14];

    const int N = in_sizes[0] / H;
    const int E = in_sizes[1] / 2;

    float* agg = nullptr;
    float* h1 = nullptr;
    unsigned char* wimg = nullptr;
    cudaGetSymbolAddress((void**)&agg, g_agg);
    cudaGetSymbolAddress((void**)&h1, g_h1);
    cudaGetSymbolAddress((void**)&wimg, g_wimg);

    cudaFuncSetAttribute((const void*)layer_mma<1>,
                         cudaFuncAttributeMaxDynamicSharedMemorySize, L_SMEM);
    cudaFuncSetAttribute((const void*)layer_mma<2>,
                         cudaFuncAttributeMaxDynamicSharedMemorySize, L_SMEM);

    // 0) pre-convert weights to MMA-ready swizzled bf16 hi/lo images
    wconv_kernel<<<256, 256>>>(W1, W2, W3);
    // 1) zero agg
    zero_kernel<<<592, 256>>>(N * (H / 4));
    // 2) scatter edges into agg
    {
        long long total = (long long)E * 32;
        int blocks = (int)((total + 255) / 256);
        scatter_kernel<<<blocks, 256>>>(ea, ei, E);
    }
    // 3) three tensor-core layers
    int nb = (N + 127) / 128;
    layer_mma<2><<<nb, 256, L_SMEM>>>(x, agg, wimg, b1, g1, be1, h1, N);
    layer_mma<1><<<nb, 256, L_SMEM>>>(h1, nullptr, wimg + 2 * 65536, b2, g2, be2, agg, N);
    layer_mma<1><<<nb, 256, L_SMEM>>>(agg, nullptr, wimg + 3 * 65536, b3, g3, be3,
                                      (float*)d_out, N);
}

// round 15
// speedup vs baseline: 2.2680x; 1.0808x over previous
#include <cuda_runtime.h>
#include <cuda_bf16.h>
#include <cstdint>

#define H 128
#define NMAX 100096
#define NTILES_MAX (NMAX / 128)          // 782
#define TILE_BYTES 65536                 // 128x128 bf16 hi (32K) + lo (32K)

// f32 scratch
static __device__ __align__(16) float g_agg[(size_t)NMAX * H];
static __device__ __align__(16) float g_h1[(size_t)NMAX * H];   // L1 partial
// bf16 hi/lo swizzled tile images
static __device__ __align__(16) unsigned char g_tx[(size_t)NTILES_MAX * TILE_BYTES];
static __device__ __align__(16) unsigned char g_ta[(size_t)NTILES_MAX * TILE_BYTES];
// weight images: chunk0=W1[k<128], 1=W1[k>=128], 2=W2, 3=W3
static __device__ __align__(16) unsigned char g_wimg[4 * 65536];

// ---------------------------------------------------------------------------
// Swizzled [row][k] bf16 tile addressing: rowbytes=256, XOR-16B on (row&7).
// ---------------------------------------------------------------------------
__device__ __forceinline__ int sw(int r, int kbyte) {
    return r * 256 + (kbyte ^ ((r & 7) << 4));
}

#define LDSM_X4(r0, r1, r2, r3, addr) \
    asm volatile("ldmatrix.sync.aligned.m8n8.x4.shared.b16 {%0,%1,%2,%3}, [%4];" \
                 : "=r"(r0), "=r"(r1), "=r"(r2), "=r"(r3) : "r"(addr))

#define MMA_BF16(c, a0, a1, a2, a3, b0, b1) \
    asm volatile("mma.sync.aligned.m16n8k16.row.col.f32.bf16.bf16.f32 " \
                 "{%0,%1,%2,%3}, {%4,%5,%6,%7}, {%8,%9}, {%0,%1,%2,%3};" \
                 : "+f"((c)[0]), "+f"((c)[1]), "+f"((c)[2]), "+f"((c)[3]) \
                 : "r"(a0), "r"(a1), "r"(a2), "r"(a3), "r"(b0), "r"(b1))

#define CP_ASYNC16(dst, src) \
    asm volatile("cp.async.cg.shared.global [%0], [%1], 16;" :: "r"(dst), "l"(src))
#define CP_COMMIT() asm volatile("cp.async.commit_group;" ::: "memory")
#define CP_WAIT1() asm volatile("cp.async.wait_group 1;" ::: "memory")

__device__ __forceinline__ uint32_t smem_u32(const void* p) {
    uint32_t a;
    asm("{ .reg .u64 t; cvta.to.shared.u64 t, %1; cvt.u32.u64 %0, t; }"
        : "=r"(a) : "l"(p));
    return a;
}

// hi/lo bf16 split-store of a float4 (4 elems -> 8B hi + 8B lo)
__device__ __forceinline__ void split_store(char* base, int off, float4 v, int lo_delta) {
    __nv_bfloat162 hA = __floats2bfloat162_rn(v.x, v.y);
    __nv_bfloat162 hB = __floats2bfloat162_rn(v.z, v.w);
    float2 fA = __bfloat1622float2(hA);
    float2 fB = __bfloat1622float2(hB);
    __nv_bfloat162 lA = __floats2bfloat162_rn(v.x - fA.x, v.y - fA.y);
    __nv_bfloat162 lB = __floats2bfloat162_rn(v.z - fB.x, v.w - fB.y);
    *reinterpret_cast<uint2*>(base + off) =
        make_uint2(*reinterpret_cast<unsigned*>(&hA), *reinterpret_cast<unsigned*>(&hB));
    *reinterpret_cast<uint2*>(base + lo_delta + off) =
        make_uint2(*reinterpret_cast<unsigned*>(&lA), *reinterpret_cast<unsigned*>(&lB));
}

// 2-element hi/lo store (epilogue -> gmem tile image)
__device__ __forceinline__ void store_hilo2(char* base, int off, float a, float b) {
    __nv_bfloat162 h = __floats2bfloat162_rn(a, b);
    float2 f = __bfloat1622float2(h);
    __nv_bfloat162 l = __floats2bfloat162_rn(a - f.x, b - f.y);
    *reinterpret_cast<uint32_t*>(base + off) = *reinterpret_cast<uint32_t*>(&h);
    *reinterpret_cast<uint32_t*>(base + off + 32768) = *reinterpret_cast<uint32_t*>(&l);
}

// ---------------------------------------------------------------------------
// Weight pre-convert: W[k][n] f32 -> [n][k] swizzled bf16 hi/lo images.
// ---------------------------------------------------------------------------
__global__ void wconv_kernel(const float* __restrict__ W1, const float* __restrict__ W2,
                             const float* __restrict__ W3) {
    int i = blockIdx.x * 256 + threadIdx.x;
    if (i >= 4 * 16384) return;
    int chunk = i >> 14;
    int idx = i & 16383;
    int n = idx & 127;
    int k = idx >> 7;
    const float* W = (chunk < 2) ? W1 : (chunk == 2 ? W2 : W3);
    int krow = (chunk == 1) ? k + 128 : k;
    float w = W[krow * H + n];
    __nv_bfloat16 hi = __float2bfloat16(w);
    __nv_bfloat16 lo = __float2bfloat16(w - __bfloat162float(hi));
    unsigned char* base = g_wimg + (size_t)chunk * 65536;
    int off = sw(n, k * 2);
    *reinterpret_cast<__nv_bfloat16*>(base + off) = hi;
    *reinterpret_cast<__nv_bfloat16*>(base + 32768 + off) = lo;
}

// ---------------------------------------------------------------------------
// f32 [N][128] -> bf16 hi/lo swizzled tile image (rows >= N zero-padded).
// ---------------------------------------------------------------------------
__global__ void conv_tiles(const float* __restrict__ src, unsigned char* __restrict__ dst,
                           int N, int total) {
    int i = blockIdx.x * 256 + threadIdx.x;
    if (i >= total) return;                 // total = ntiles*4096
    int tile = i >> 12;
    int u = i & 4095;
    int r = u >> 5, kc = u & 31;
    int row = tile * 128 + r;
    float4 v = make_float4(0.f, 0.f, 0.f, 0.f);
    if (row < N) v = reinterpret_cast<const float4*>(src)[(size_t)row * 32 + kc];
    split_store(reinterpret_cast<char*>(dst) + (size_t)tile * TILE_BYTES,
                sw(r, kc * 8), v, 32768);
}

// ---------------------------------------------------------------------------
// Persistent fused layer: D = A @ W (+partial) (+bias+LN+ssp)
// MODE 0: raw f32 partial out. MODE 1: bf16 hi/lo tile out. MODE 2: f32 final.
// smem: [B 64K][A buf0 64K][A buf1 64K][params]
// ---------------------------------------------------------------------------
#define SM_A0 65536
#define SM_P 196608
#define L_SMEM (196608 + 2048)

template <int MODE, bool ADDP>
__global__ __launch_bounds__(256, 1)
void layer_pp(const unsigned char* __restrict__ atiles,
              const unsigned char* __restrict__ wimg,
              const float* __restrict__ partial,
              const float* __restrict__ bias, const float* __restrict__ gam,
              const float* __restrict__ bet, void* __restrict__ outp,
              int N, int ntiles) {
    extern __shared__ char smem[];
    const int tid = threadIdx.x;
    const int lane = tid & 31;
    const int wid = tid >> 5;
    const uint32_t sb = smem_u32(smem);
    const int stride = gridDim.x;

    float* sBias = reinterpret_cast<float*>(smem + SM_P);
    float* sG = sBias + 128;
    float* sBe = sG + 128;
    if (MODE != 0 && tid < 128) {
        sBias[tid] = bias[tid];
        sG[tid] = gam[tid];
        sBe[tid] = bet[tid];
    }

    // Prologue: B (resident) + A tile0 -> buf0, one commit group.
    #pragma unroll
    for (int j = 0; j < 16; j++) {
        int u = tid + j * 256;
        CP_ASYNC16(sb + u * 16, wimg + u * 16);
    }
    {
        const unsigned char* src = atiles + (size_t)blockIdx.x * TILE_BYTES;
        #pragma unroll
        for (int j = 0; j < 16; j++) {
            int u = tid + j * 256;
            CP_ASYNC16(sb + SM_A0 + u * 16, src + u * 16);
        }
    }
    CP_COMMIT();

    // Lane-invariant LDSM addressing (same fragment layout as validated R14)
    const int wbase = wid * 16;
    const int rowA = wbase + (lane & 15);
    const uint32_t aOff = rowA * 256;
    const int xorA = (rowA & 7) << 4;
    const int kbSelA = (lane >> 4) << 4;
    const int nLane = lane & 7;
    const uint32_t bBase0 = sb + ((lane >> 4) & 1) * 32768 + nLane * 256;
    const int xorB = nLane << 4;
    const int kbSelB = ((lane >> 3) & 1) << 4;

    const int g = lane >> 2, tg = lane & 3;

    int it = 0;
    for (int t = blockIdx.x; t < ntiles; t += stride, it++) {
        const int b = it & 1;
        // Issue next tile into the other buffer (empty group if out of range).
        int tn = t + stride;
        if (tn < ntiles) {
            const unsigned char* src = atiles + (size_t)tn * TILE_BYTES;
            uint32_t dst = sb + SM_A0 + ((b ^ 1) << 16);
            #pragma unroll
            for (int j = 0; j < 16; j++) {
                int u = tid + j * 256;
                CP_ASYNC16(dst + u * 16, src + u * 16);
            }
        }
        CP_COMMIT();
        CP_WAIT1();          // current tile (and B) complete
        __syncthreads();

        // ---- MMA phase on buffer b ----
        float acc[16][4];
        #pragma unroll
        for (int j = 0; j < 16; j++)
            #pragma unroll
            for (int u = 0; u < 4; u++) acc[j][u] = 0.f;

        const uint32_t aBuf = sb + SM_A0 + (b << 16) + aOff;
        #pragma unroll
        for (int s = 0; s < 8; s++) {
            uint32_t aaddr = aBuf + ((s * 32 + kbSelA) ^ xorA);
            uint32_t ah0, ah1, ah2, ah3, al0, al1, al2, al3;
            LDSM_X4(ah0, ah1, ah2, ah3, aaddr);
            LDSM_X4(al0, al1, al2, al3, aaddr + 32768);
            uint32_t bbase = bBase0 + ((s * 32 + kbSelB) ^ xorB);
            #pragma unroll
            for (int j = 0; j < 16; j++) {
                uint32_t bh0, bh1, bl0, bl1;
                LDSM_X4(bh0, bh1, bl0, bl1, bbase + j * 2048);
                MMA_BF16(acc[j], ah0, ah1, ah2, ah3, bh0, bh1);
                MMA_BF16(acc[j], ah0, ah1, ah2, ah3, bl0, bl1);
                MMA_BF16(acc[j], al0, al1, al2, al3, bh0, bh1);
            }
        }
        __syncthreads();   // done reading buf b; next iter may overwrite it

        // ---- Epilogue for tile t ----
        const int row0 = t * 128;
        const int rl0 = wbase + g;          // local rows
        const int rl1 = rl0 + 8;
        const int r0g = row0 + rl0;
        const int r1g = row0 + rl1;
        const bool ok0 = r0g < N, ok1 = r1g < N;

        if (ADDP) {
            #pragma unroll
            for (int j = 0; j < 16; j++) {
                int col = j * 8 + 2 * tg;
                float2 p0 = *reinterpret_cast<const float2*>(partial + (size_t)r0g * H + col);
                float2 p1 = *reinterpret_cast<const float2*>(partial + (size_t)r1g * H + col);
                acc[j][0] += p0.x; acc[j][1] += p0.y;
                acc[j][2] += p1.x; acc[j][3] += p1.y;
            }
        }

        if (MODE == 0) {
            float* outf = reinterpret_cast<float*>(outp);
            #pragma unroll
            for (int j = 0; j < 16; j++) {
                int col = j * 8 + 2 * tg;
                if (ok0)
                    *reinterpret_cast<float2*>(outf + (size_t)r0g * H + col) =
                        make_float2(acc[j][0], acc[j][1]);
                if (ok1)
                    *reinterpret_cast<float2*>(outf + (size_t)r1g * H + col) =
                        make_float2(acc[j][2], acc[j][3]);
            }
        } else {
            float s0 = 0.f, q0 = 0.f, s1 = 0.f, q1 = 0.f;
            #pragma unroll
            for (int j = 0; j < 16; j++) {
                float2 bv = *reinterpret_cast<const float2*>(&sBias[j * 8 + 2 * tg]);
                acc[j][0] += bv.x; acc[j][1] += bv.y;
                acc[j][2] += bv.x; acc[j][3] += bv.y;
                s0 += acc[j][0] + acc[j][1];
                q0 += acc[j][0] * acc[j][0] + acc[j][1] * acc[j][1];
                s1 += acc[j][2] + acc[j][3];
                q1 += acc[j][2] * acc[j][2] + acc[j][3] * acc[j][3];
            }
            #pragma unroll
            for (int m = 1; m <= 2; m <<= 1) {
                s0 += __shfl_xor_sync(0xffffffffu, s0, m);
                q0 += __shfl_xor_sync(0xffffffffu, q0, m);
                s1 += __shfl_xor_sync(0xffffffffu, s1, m);
                q1 += __shfl_xor_sync(0xffffffffu, q1, m);
            }
            const float inv = 1.0f / 128.0f;
            float mean0 = s0 * inv, mean1 = s1 * inv;
            float rs0 = rsqrtf(q0 * inv - mean0 * mean0 + 1e-5f);
            float rs1 = rsqrtf(q1 * inv - mean1 * mean1 + 1e-5f);
            const float LN2 = 0.6931471805599453f;
            char* outTile = reinterpret_cast<char*>(outp) + (size_t)t * TILE_BYTES;
            float* outf = reinterpret_cast<float*>(outp);
            #pragma unroll
            for (int j = 0; j < 16; j++) {
                int col = j * 8 + 2 * tg;
                float2 gv = *reinterpret_cast<const float2*>(&sG[col]);
                float2 ev = *reinterpret_cast<const float2*>(&sBe[col]);
                float y00 = (acc[j][0] - mean0) * rs0 * gv.x + ev.x;
                float y01 = (acc[j][1] - mean0) * rs0 * gv.y + ev.y;
                float y10 = (acc[j][2] - mean1) * rs1 * gv.x + ev.x;
                float y11 = (acc[j][3] - mean1) * rs1 * gv.y + ev.y;
                float o00 = fmaxf(y00, 0.f) + log1pf(__expf(-fabsf(y00))) - LN2;
                float o01 = fmaxf(y01, 0.f) + log1pf(__expf(-fabsf(y01))) - LN2;
                float o10 = fmaxf(y10, 0.f) + log1pf(__expf(-fabsf(y10))) - LN2;
                float o11 = fmaxf(y11, 0.f) + log1pf(__expf(-fabsf(y11))) - LN2;
                if (MODE == 1) {
                    if (ok0) store_hilo2(outTile, sw(rl0, col * 2), o00, o01);
                    if (ok1) store_hilo2(outTile, sw(rl1, col * 2), o10, o11);
                } else {
                    if (ok0)
                        *reinterpret_cast<float2*>(outf + (size_t)r0g * H + col) =
                            make_float2(o00, o01);
                    if (ok1)
                        *reinterpret_cast<float2*>(outf + (size_t)r1g * H + col) =
                            make_float2(o10, o11);
                }
            }
        }
    }
}

// ---------------------------------------------------------------------------
// Zero + scatter (unchanged)
// ---------------------------------------------------------------------------
__global__ void zero_kernel(int n4) {
    float4* p = reinterpret_cast<float4*>(g_agg);
    int i = blockIdx.x * blockDim.x + threadIdx.x;
    int stride = gridDim.x * blockDim.x;
    float4 z = make_float4(0.f, 0.f, 0.f, 0.f);
    for (; i < n4; i += stride) p[i] = z;
}

__global__ void scatter_kernel(const float* __restrict__ ea,
                               const int* __restrict__ ei32, int E) {
    long long i = (long long)blockIdx.x * blockDim.x + threadIdx.x;
    long long total = (long long)E * 32;
    if (i >= total) return;
    int e = (int)(i >> 5);
    int q = (int)(i & 31);
    bool is64 = ((ei32[1] | ei32[3] | ei32[5] | ei32[7]) == 0);
    int col = is64 ? ei32[2 * (E + e)] : ei32[E + e];
    float4 v = reinterpret_cast<const float4*>(ea)[(size_t)e * 32 + q];
    float* dst = g_agg + (size_t)col * H + q * 4;
    asm volatile("red.global.add.v4.f32 [%0], {%1,%2,%3,%4};"
                 :: "l"(dst), "f"(v.x), "f"(v.y), "f"(v.z), "f"(v.w)
                 : "memory");
}

// ---------------------------------------------------------------------------
// Launch
// ---------------------------------------------------------------------------
extern "C" void kernel_launch(void* const* d_in, const int* in_sizes, int n_in,
                              void* d_out, int out_size) {
    const float* x   = (const float*)d_in[0];
    const int* ei    = (const int*)d_in[1];
    const float* ea  = (const float*)d_in[2];
    const float* W1  = (const float*)d_in[3];
    const float* b1  = (const float*)d_in[4];
    const float* g1  = (const float*)d_in[5];
    const float* be1 = (const float*)d_in[6];
    const float* W2  = (const float*)d_in[7];
    const float* b2  = (const float*)d_in[8];
    const float* g2  = (const float*)d_in[9];
    const float* be2 = (const float*)d_in[10];
    const float* W3  = (const float*)d_in[11];
    const float* b3  = (const float*)d_in[12];
    const float* g3  = (const float*)d_in[13];
    const float* be3 = (const float*)d_in[14];

    const int N = in_sizes[0] / H;
    const int E = in_sizes[1] / 2;
    const int ntiles = (N + 127) / 128;

    float* agg = nullptr; float* h1 = nullptr;
    unsigned char *wimg = nullptr, *tx = nullptr, *ta = nullptr;
    cudaGetSymbolAddress((void**)&agg, g_agg);
    cudaGetSymbolAddress((void**)&h1, g_h1);
    cudaGetSymbolAddress((void**)&wimg, g_wimg);
    cudaGetSymbolAddress((void**)&tx, g_tx);
    cudaGetSymbolAddress((void**)&ta, g_ta);

    int sms = 148;
    cudaDeviceGetAttribute(&sms, cudaDevAttrMultiProcessorCount, 0);

    cudaFuncSetAttribute((const void*)layer_pp<0, false>,
                         cudaFuncAttributeMaxDynamicSharedMemorySize, L_SMEM);
    cudaFuncSetAttribute((const void*)layer_pp<1, true>,
                         cudaFuncAttributeMaxDynamicSharedMemorySize, L_SMEM);
    cudaFuncSetAttribute((const void*)layer_pp<1, false>,
                         cudaFuncAttributeMaxDynamicSharedMemorySize, L_SMEM);
    cudaFuncSetAttribute((const void*)layer_pp<2, false>,
                         cudaFuncAttributeMaxDynamicSharedMemorySize, L_SMEM);

    // 0) weight images + x tiles + zero agg
    wconv_kernel<<<256, 256>>>(W1, W2, W3);
    conv_tiles<<<ntiles * 16, 256>>>(x, tx, N, ntiles * 4096);
    zero_kernel<<<592, 256>>>(N * (H / 4));
    // 1) scatter
    {
        long long total = (long long)E * 32;
        int blocks = (int)((total + 255) / 256);
        scatter_kernel<<<blocks, 256>>>(ea, ei, E);
    }
    // 2) agg tiles
    conv_tiles<<<ntiles * 16, 256>>>(agg, ta, N, ntiles * 4096);
    // 3) layers: L1a (x part -> partial), L1b (agg part + partial -> h1 tiles in g_tx),
    //    L2 (g_tx -> g_ta tiles), L3 (g_ta -> f32 d_out)
    layer_pp<0, false><<<sms, 256, L_SMEM>>>(tx, wimg, nullptr, nullptr, nullptr, nullptr,
                                             h1, N, ntiles);
    layer_pp<1, true><<<sms, 256, L_SMEM>>>(ta, wimg + 65536, h1, b1, g1, be1,
                                            tx, N, ntiles);
    layer_pp<1, false><<<sms, 256, L_SMEM>>>(tx, wimg + 2 * 65536, nullptr, b2, g2, be2,
                                             ta, N, ntiles);
    layer_pp<2, false><<<sms, 256, L_SMEM>>>(ta, wimg + 3 * 65536, nullptr, b3, g3, be3,
                                             d_out, N, ntiles);
}

// round 16
// speedup vs baseline: 2.3174x; 1.0218x over previous
#include <cuda_runtime.h>
#include <cuda_bf16.h>
#include <cstdint>

#define H 128
#define NMAX 100096
#define NTILES_MAX (NMAX / 128)          // 782
#define TILE_BYTES 65536                 // 128x128 bf16 hi (32K) + lo (32K)

// f32 scratch
static __device__ __align__(16) float g_agg[(size_t)NMAX * H];
static __device__ __align__(16) float g_h1[(size_t)NMAX * H];   // L1 partial
// bf16 hi/lo swizzled tile images
static __device__ __align__(16) unsigned char g_tx[(size_t)NTILES_MAX * TILE_BYTES];
static __device__ __align__(16) unsigned char g_ta[(size_t)NTILES_MAX * TILE_BYTES];
// weight images: chunk0=W1[k<128], 1=W1[k>=128], 2=W2, 3=W3
static __device__ __align__(16) unsigned char g_wimg[4 * 65536];

// ---------------------------------------------------------------------------
// Swizzled [row][k] bf16 tile addressing: rowbytes=256, XOR-16B on (row&7).
// ---------------------------------------------------------------------------
__device__ __forceinline__ int sw(int r, int kbyte) {
    return r * 256 + (kbyte ^ ((r & 7) << 4));
}

#define LDSM_X4(r0, r1, r2, r3, addr) \
    asm volatile("ldmatrix.sync.aligned.m8n8.x4.shared.b16 {%0,%1,%2,%3}, [%4];" \
                 : "=r"(r0), "=r"(r1), "=r"(r2), "=r"(r3) : "r"(addr))

#define MMA_BF16(c, a0, a1, a2, a3, b0, b1) \
    asm volatile("mma.sync.aligned.m16n8k16.row.col.f32.bf16.bf16.f32 " \
                 "{%0,%1,%2,%3}, {%4,%5,%6,%7}, {%8,%9}, {%0,%1,%2,%3};" \
                 : "+f"((c)[0]), "+f"((c)[1]), "+f"((c)[2]), "+f"((c)[3]) \
                 : "r"(a0), "r"(a1), "r"(a2), "r"(a3), "r"(b0), "r"(b1))

// 1D bulk async copy gmem->smem with mbarrier completion (SASS: UBLKCP.S.G)
#define TMA_BULK_G2S(dst, src, bytes, mbar) \
    asm volatile("cp.async.bulk.shared::cluster.global.mbarrier::complete_tx::bytes " \
                 "[%0], [%1], %2, [%3];" \
                 :: "r"(dst), "l"(src), "r"(bytes), "r"(mbar) : "memory")

#define MBARRIER_INIT(addr, cnt) \
    asm volatile("mbarrier.init.shared.b64 [%0], %1;" :: "r"(addr), "r"(cnt) : "memory")
#define MBARRIER_EXPECT_TX(addr, bytes) \
    asm volatile("mbarrier.arrive.expect_tx.shared.b64 _, [%0], %1;" \
                 :: "r"(addr), "r"(bytes) : "memory")

#define MBARRIER_WAIT_PARITY(mbar_smem_addr, phase_parity) do { \
    uint32_t _mbar = (uint32_t)(mbar_smem_addr); \
    uint32_t _parity = (uint32_t)(phase_parity); \
    uint32_t _done; \
    asm volatile("{\n\t.reg .pred p;\n\t" \
        "mbarrier.try_wait.parity.acquire.cta.shared::cta.b64 p, [%1], %2;\n\t" \
        "selp.b32 %0, 1, 0, p;\n\t}" \
        : "=r"(_done) : "r"(_mbar), "r"(_parity) : "memory"); \
    if (!_done) { \
        asm volatile("{\n\t.reg .pred P1;\n\t" \
            "WAIT_LOOP_%=:\n\t" \
            "mbarrier.try_wait.parity.acquire.cta.shared::cta.b64 P1, [%0], %1, 0x989680;\n\t" \
            "@P1 bra.uni WAIT_DONE_%=;\n\t" \
            "bra.uni WAIT_LOOP_%=;\n\t" \
            "WAIT_DONE_%=:\n\t}" \
            :: "r"(_mbar), "r"(_parity) : "memory"); \
    } \
} while (0)

__device__ __forceinline__ uint32_t smem_u32(const void* p) {
    uint32_t a;
    asm("{ .reg .u64 t; cvta.to.shared.u64 t, %1; cvt.u32.u64 %0, t; }"
        : "=r"(a) : "l"(p));
    return a;
}

// hi/lo bf16 split-store of a float4 (4 elems -> 8B hi + 8B lo)
__device__ __forceinline__ void split_store(char* base, int off, float4 v, int lo_delta) {
    __nv_bfloat162 hA = __floats2bfloat162_rn(v.x, v.y);
    __nv_bfloat162 hB = __floats2bfloat162_rn(v.z, v.w);
    float2 fA = __bfloat1622float2(hA);
    float2 fB = __bfloat1622float2(hB);
    __nv_bfloat162 lA = __floats2bfloat162_rn(v.x - fA.x, v.y - fA.y);
    __nv_bfloat162 lB = __floats2bfloat162_rn(v.z - fB.x, v.w - fB.y);
    *reinterpret_cast<uint2*>(base + off) =
        make_uint2(*reinterpret_cast<unsigned*>(&hA), *reinterpret_cast<unsigned*>(&hB));
    *reinterpret_cast<uint2*>(base + lo_delta + off) =
        make_uint2(*reinterpret_cast<unsigned*>(&lA), *reinterpret_cast<unsigned*>(&lB));
}

// 2-element hi/lo store (epilogue -> gmem tile image)
__device__ __forceinline__ void store_hilo2(char* base, int off, float a, float b) {
    __nv_bfloat162 h = __floats2bfloat162_rn(a, b);
    float2 f = __bfloat1622float2(h);
    __nv_bfloat162 l = __floats2bfloat162_rn(a - f.x, b - f.y);
    *reinterpret_cast<uint32_t*>(base + off) = *reinterpret_cast<uint32_t*>(&h);
    *reinterpret_cast<uint32_t*>(base + off + 32768) = *reinterpret_cast<uint32_t*>(&l);
}

// ---------------------------------------------------------------------------
// Weight pre-convert: W[k][n] f32 -> [n][k] swizzled bf16 hi/lo images.
// ---------------------------------------------------------------------------
__global__ void wconv_kernel(const float* __restrict__ W1, const float* __restrict__ W2,
                             const float* __restrict__ W3) {
    int i = blockIdx.x * 256 + threadIdx.x;
    if (i >= 4 * 16384) return;
    int chunk = i >> 14;
    int idx = i & 16383;
    int n = idx & 127;
    int k = idx >> 7;
    const float* W = (chunk < 2) ? W1 : (chunk == 2 ? W2 : W3);
    int krow = (chunk == 1) ? k + 128 : k;
    float w = W[krow * H + n];
    __nv_bfloat16 hi = __float2bfloat16(w);
    __nv_bfloat16 lo = __float2bfloat16(w - __bfloat162float(hi));
    unsigned char* base = g_wimg + (size_t)chunk * 65536;
    int off = sw(n, k * 2);
    *reinterpret_cast<__nv_bfloat16*>(base + off) = hi;
    *reinterpret_cast<__nv_bfloat16*>(base + 32768 + off) = lo;
}

// ---------------------------------------------------------------------------
// f32 [N][128] -> bf16 hi/lo swizzled tile image (rows >= N zero-padded).
// ---------------------------------------------------------------------------
__global__ void conv_tiles(const float* __restrict__ src, unsigned char* __restrict__ dst,
                           int N, int total) {
    int i = blockIdx.x * 256 + threadIdx.x;
    if (i >= total) return;                 // total = ntiles*4096
    int tile = i >> 12;
    int u = i & 4095;
    int r = u >> 5, kc = u & 31;
    int row = tile * 128 + r;
    float4 v = make_float4(0.f, 0.f, 0.f, 0.f);
    if (row < N) v = reinterpret_cast<const float4*>(src)[(size_t)row * 32 + kc];
    split_store(reinterpret_cast<char*>(dst) + (size_t)tile * TILE_BYTES,
                sw(r, kc * 8), v, 32768);
}

// ---------------------------------------------------------------------------
// Persistent fused layer with bulk-async staging.
// MODE 0: raw f32 partial out. MODE 1: bf16 hi/lo tile out. MODE 2: f32 final.
// smem: [B 64K][A buf0 64K][A buf1 64K][params 1.5K][mbar x2]
// ---------------------------------------------------------------------------
#define SM_A0 65536
#define SM_P 196608
#define SM_MB (196608 + 1536)
#define L_SMEM (196608 + 2048)

template <int MODE, bool ADDP>
__global__ __launch_bounds__(256, 1)
void layer_tma(const unsigned char* __restrict__ atiles,
               const unsigned char* __restrict__ wimg,
               const float* __restrict__ partial,
               const float* __restrict__ bias, const float* __restrict__ gam,
               const float* __restrict__ bet, void* __restrict__ outp,
               int N, int ntiles) {
    extern __shared__ char smem[];
    const int tid = threadIdx.x;
    const int lane = tid & 31;
    const int wid = tid >> 5;
    const uint32_t sb = smem_u32(smem);
    const uint32_t mb = sb + SM_MB;
    const int stride = gridDim.x;

    float* sBias = reinterpret_cast<float*>(smem + SM_P);
    float* sG = sBias + 128;
    float* sBe = sG + 128;
    if (MODE != 0 && tid < 128) {
        sBias[tid] = bias[tid];
        sG[tid] = gam[tid];
        sBe[tid] = bet[tid];
    }
    if (tid == 0) {
        MBARRIER_INIT(mb, 1);
        MBARRIER_INIT(mb + 8, 1);
    }
    __syncthreads();   // barriers visible before any expect/wait

    // Prologue: B (resident) + A tile0 -> buf0 on barrier 0.
    if (tid == 0) {
        MBARRIER_EXPECT_TX(mb, 131072);
        TMA_BULK_G2S(sb, wimg, 65536, mb);
        TMA_BULK_G2S(sb + SM_A0, atiles + (size_t)blockIdx.x * TILE_BYTES, 65536, mb);
    }

    // Lane-invariant LDSM addressing (validated fragment layout)
    const int wbase = wid * 16;
    const int rowA = wbase + (lane & 15);
    const uint32_t aOff = rowA * 256;
    const int xorA = (rowA & 7) << 4;
    const int kbSelA = (lane >> 4) << 4;
    const int nLane = lane & 7;
    const uint32_t bBase0 = sb + ((lane >> 4) & 1) * 32768 + nLane * 256;
    const int xorB = nLane << 4;
    const int kbSelB = ((lane >> 3) & 1) << 4;

    const int g = lane >> 2, tg = lane & 3;

    int ph0 = 0, ph1 = 0;
    int it = 0;
    for (int t = blockIdx.x; t < ntiles; t += stride, it++) {
        const int b = it & 1;
        // Kick off next tile into the other buffer (it was drained last iter).
        int tn = t + stride;
        if (tid == 0 && tn < ntiles) {
            uint32_t mbn = mb + ((b ^ 1) << 3);
            MBARRIER_EXPECT_TX(mbn, 65536);
            TMA_BULK_G2S(sb + SM_A0 + ((b ^ 1) << 16),
                         atiles + (size_t)tn * TILE_BYTES, 65536, mbn);
        }
        // Wait for current buffer (all threads; acquire orders LDSM after TMA).
        if (b == 0) { MBARRIER_WAIT_PARITY(mb, ph0); ph0 ^= 1; }
        else        { MBARRIER_WAIT_PARITY(mb + 8, ph1); ph1 ^= 1; }

        // ---- MMA phase on buffer b ----
        float acc[16][4];
        #pragma unroll
        for (int j = 0; j < 16; j++)
            #pragma unroll
            for (int u = 0; u < 4; u++) acc[j][u] = 0.f;

        const uint32_t aBuf = sb + SM_A0 + (b << 16) + aOff;
        #pragma unroll
        for (int s = 0; s < 8; s++) {
            uint32_t aaddr = aBuf + ((s * 32 + kbSelA) ^ xorA);
            uint32_t ah0, ah1, ah2, ah3, al0, al1, al2, al3;
            LDSM_X4(ah0, ah1, ah2, ah3, aaddr);
            LDSM_X4(al0, al1, al2, al3, aaddr + 32768);
            uint32_t bbase = bBase0 + ((s * 32 + kbSelB) ^ xorB);
            #pragma unroll
            for (int j = 0; j < 16; j++) {
                uint32_t bh0, bh1, bl0, bl1;
                LDSM_X4(bh0, bh1, bl0, bl1, bbase + j * 2048);
                MMA_BF16(acc[j], ah0, ah1, ah2, ah3, bh0, bh1);
                MMA_BF16(acc[j], ah0, ah1, ah2, ah3, bl0, bl1);
                MMA_BF16(acc[j], al0, al1, al2, al3, bh0, bh1);
            }
        }
        __syncthreads();   // all warps done reading buf b before it is refilled

        // ---- Epilogue for tile t ----
        const int row0 = t * 128;
        const int rl0 = wbase + g;
        const int rl1 = rl0 + 8;
        const int r0g = row0 + rl0;
        const int r1g = row0 + rl1;
        const bool ok0 = r0g < N, ok1 = r1g < N;

        if (ADDP) {
            #pragma unroll
            for (int j = 0; j < 16; j++) {
                int col = j * 8 + 2 * tg;
                float2 p0 = *reinterpret_cast<const float2*>(partial + (size_t)r0g * H + col);
                float2 p1 = *reinterpret_cast<const float2*>(partial + (size_t)r1g * H + col);
                acc[j][0] += p0.x; acc[j][1] += p0.y;
                acc[j][2] += p1.x; acc[j][3] += p1.y;
            }
        }

        if (MODE == 0) {
            float* outf = reinterpret_cast<float*>(outp);
            #pragma unroll
            for (int j = 0; j < 16; j++) {
                int col = j * 8 + 2 * tg;
                if (ok0)
                    *reinterpret_cast<float2*>(outf + (size_t)r0g * H + col) =
                        make_float2(acc[j][0], acc[j][1]);
                if (ok1)
                    *reinterpret_cast<float2*>(outf + (size_t)r1g * H + col) =
                        make_float2(acc[j][2], acc[j][3]);
            }
        } else {
            float s0 = 0.f, q0 = 0.f, s1 = 0.f, q1 = 0.f;
            #pragma unroll
            for (int j = 0; j < 16; j++) {
                float2 bv = *reinterpret_cast<const float2*>(&sBias[j * 8 + 2 * tg]);
                acc[j][0] += bv.x; acc[j][1] += bv.y;
                acc[j][2] += bv.x; acc[j][3] += bv.y;
                s0 += acc[j][0] + acc[j][1];
                q0 += acc[j][0] * acc[j][0] + acc[j][1] * acc[j][1];
                s1 += acc[j][2] + acc[j][3];
                q1 += acc[j][2] * acc[j][2] + acc[j][3] * acc[j][3];
            }
            #pragma unroll
            for (int m = 1; m <= 2; m <<= 1) {
                s0 += __shfl_xor_sync(0xffffffffu, s0, m);
                q0 += __shfl_xor_sync(0xffffffffu, q0, m);
                s1 += __shfl_xor_sync(0xffffffffu, s1, m);
                q1 += __shfl_xor_sync(0xffffffffu, q1, m);
            }
            const float inv = 1.0f / 128.0f;
            float mean0 = s0 * inv, mean1 = s1 * inv;
            float rs0 = rsqrtf(q0 * inv - mean0 * mean0 + 1e-5f);
            float rs1 = rsqrtf(q1 * inv - mean1 * mean1 + 1e-5f);
            const float LN2 = 0.6931471805599453f;
            char* outTile = reinterpret_cast<char*>(outp) + (size_t)t * TILE_BYTES;
            float* outf = reinterpret_cast<float*>(outp);
            #pragma unroll
            for (int j = 0; j < 16; j++) {
                int col = j * 8 + 2 * tg;
                float2 gv = *reinterpret_cast<const float2*>(&sG[col]);
                float2 ev = *reinterpret_cast<const float2*>(&sBe[col]);
                float y00 = (acc[j][0] - mean0) * rs0 * gv.x + ev.x;
                float y01 = (acc[j][1] - mean0) * rs0 * gv.y + ev.y;
                float y10 = (acc[j][2] - mean1) * rs1 * gv.x + ev.x;
                float y11 = (acc[j][3] - mean1) * rs1 * gv.y + ev.y;
                float o00 = fmaxf(y00, 0.f) + log1pf(__expf(-fabsf(y00))) - LN2;
                float o01 = fmaxf(y01, 0.f) + log1pf(__expf(-fabsf(y01))) - LN2;
                float o10 = fmaxf(y10, 0.f) + log1pf(__expf(-fabsf(y10))) - LN2;
                float o11 = fmaxf(y11, 0.f) + log1pf(__expf(-fabsf(y11))) - LN2;
                if (MODE == 1) {
                    if (ok0) store_hilo2(outTile, sw(rl0, col * 2), o00, o01);
                    if (ok1) store_hilo2(outTile, sw(rl1, col * 2), o10, o11);
                } else {
                    if (ok0)
                        *reinterpret_cast<float2*>(outf + (size_t)r0g * H + col) =
                            make_float2(o00, o01);
                    if (ok1)
                        *reinterpret_cast<float2*>(outf + (size_t)r1g * H + col) =
                            make_float2(o10, o11);
                }
            }
        }
    }
}

// ---------------------------------------------------------------------------
// Zero + scatter (unchanged — scatter is at 74.8% of HBM roofline)
// ---------------------------------------------------------------------------
__global__ void zero_kernel(int n4) {
    float4* p = reinterpret_cast<float4*>(g_agg);
    int i = blockIdx.x * blockDim.x + threadIdx.x;
    int stride = gridDim.x * blockDim.x;
    float4 z = make_float4(0.f, 0.f, 0.f, 0.f);
    for (; i < n4; i += stride) p[i] = z;
}

__global__ void scatter_kernel(const float* __restrict__ ea,
                               const int* __restrict__ ei32, int E) {
    long long i = (long long)blockIdx.x * blockDim.x + threadIdx.x;
    long long total = (long long)E * 32;
    if (i >= total) return;
    int e = (int)(i >> 5);
    int q = (int)(i & 31);
    bool is64 = ((ei32[1] | ei32[3] | ei32[5] | ei32[7]) == 0);
    int col = is64 ? ei32[2 * (E + e)] : ei32[E + e];
    float4 v = reinterpret_cast<const float4*>(ea)[(size_t)e * 32 + q];
    float* dst = g_agg + (size_t)col * H + q * 4;
    asm volatile("red.global.add.v4.f32 [%0], {%1,%2,%3,%4};"
                 :: "l"(dst), "f"(v.x), "f"(v.y), "f"(v.z), "f"(v.w)
                 : "memory");
}

// ---------------------------------------------------------------------------
// Launch
// ---------------------------------------------------------------------------
extern "C" void kernel_launch(void* const* d_in, const int* in_sizes, int n_in,
                              void* d_out, int out_size) {
    const float* x   = (const float*)d_in[0];
    const int* ei    = (const int*)d_in[1];
    const float* ea  = (const float*)d_in[2];
    const float* W1  = (const float*)d_in[3];
    const float* b1  = (const float*)d_in[4];
    const float* g1  = (const float*)d_in[5];
    const float* be1 = (const float*)d_in[6];
    const float* W2  = (const float*)d_in[7];
    const float* b2  = (const float*)d_in[8];
    const float* g2  = (const float*)d_in[9];
    const float* be2 = (const float*)d_in[10];
    const float* W3  = (const float*)d_in[11];
    const float* b3  = (const float*)d_in[12];
    const float* g3  = (const float*)d_in[13];
    const float* be3 = (const float*)d_in[14];

    const int N = in_sizes[0] / H;
    const int E = in_sizes[1] / 2;
    const int ntiles = (N + 127) / 128;

    float* agg = nullptr; float* h1 = nullptr;
    unsigned char *wimg = nullptr, *tx = nullptr, *ta = nullptr;
    cudaGetSymbolAddress((void**)&agg, g_agg);
    cudaGetSymbolAddress((void**)&h1, g_h1);
    cudaGetSymbolAddress((void**)&wimg, g_wimg);
    cudaGetSymbolAddress((void**)&tx, g_tx);
    cudaGetSymbolAddress((void**)&ta, g_ta);

    int sms = 148;
    cudaDeviceGetAttribute(&sms, cudaDevAttrMultiProcessorCount, 0);

    cudaFuncSetAttribute((const void*)layer_tma<0, false>,
                         cudaFuncAttributeMaxDynamicSharedMemorySize, L_SMEM);
    cudaFuncSetAttribute((const void*)layer_tma<1, true>,
                         cudaFuncAttributeMaxDynamicSharedMemorySize, L_SMEM);
    cudaFuncSetAttribute((const void*)layer_tma<1, false>,
                         cudaFuncAttributeMaxDynamicSharedMemorySize, L_SMEM);
    cudaFuncSetAttribute((const void*)layer_tma<2, false>,
                         cudaFuncAttributeMaxDynamicSharedMemorySize, L_SMEM);

    // 0) weight images + x tiles + zero agg
    wconv_kernel<<<256, 256>>>(W1, W2, W3);
    conv_tiles<<<ntiles * 16, 256>>>(x, tx, N, ntiles * 4096);
    zero_kernel<<<592, 256>>>(N * (H / 4));
    // 1) scatter
    {
        long long total = (long long)E * 32;
        int blocks = (int)((total + 255) / 256);
        scatter_kernel<<<blocks, 256>>>(ea, ei, E);
    }
    // 2) agg tiles
    conv_tiles<<<ntiles * 16, 256>>>(agg, ta, N, ntiles * 4096);
    // 3) layers: L1a (x part -> f32 partial), L1b (agg part + partial -> tiles in g_tx),
    //    L2 (g_tx -> tiles in g_ta), L3 (g_ta -> f32 d_out)
    layer_tma<0, false><<<sms, 256, L_SMEM>>>(tx, wimg, nullptr, nullptr, nullptr, nullptr,
                                              h1, N, ntiles);
    layer_tma<1, true><<<sms, 256, L_SMEM>>>(ta, wimg + 65536, h1, b1, g1, be1,
                                             tx, N, ntiles);
    layer_tma<1, false><<<sms, 256, L_SMEM>>>(tx, wimg + 2 * 65536, nullptr, b2, g2, be2,
                                              ta, N, ntiles);
    layer_tma<2, false><<<sms, 256, L_SMEM>>>(ta, wimg + 3 * 65536, nullptr, b3, g3, be3,
                                              d_out, N, ntiles);
}